// round 3
// baseline (speedup 1.0000x reference)
#include <cuda_runtime.h>
#include <math.h>

// Problem constants
#define NTOK   65536
#define DMODEL 1024
#define NHEAD  16
#define DHEAD  64
#define FFDIM  2048
#define EPSBN  1e-5f
#define PB     128   // BN partial row-blocks

static constexpr size_t ND = (size_t)NTOK * DMODEL;   // 67,108,864 floats = 256MB

// ---------------- scratch (device globals; total < 2GB to keep linker happy) -
// 4 slots of ND floats = 1 GiB total. Lifetime-multiplexed (see launch code).
__device__ float g_scratch[4 * ND];
__device__ float g_part[PB * 2 * DMODEL];
__device__ float g_scale[DMODEL];
__device__ float g_shift[DMODEL];

// ---------------- SGEMM: C[M,Nc] = A[M,K] @ B[K,Nc] (+epilogue) --------------
// MODE 0: plain   MODE 1: +bias, ReLU   MODE 2: +bias, +residual
#define BM 128
#define BN 128
#define BK 16

template<int MODE>
__global__ __launch_bounds__(256, 2)
void sgemm_k(const float* __restrict__ A, const float* __restrict__ B,
             const float* __restrict__ bias, const float* __restrict__ res,
             float* __restrict__ C, int Kd, int Nc)
{
    __shared__ float As[BK][BM + 4];
    __shared__ float Bs[BK][BN + 4];

    const int tid = threadIdx.x;              // 0..255
    const int tx  = tid & 15;
    const int ty  = tid >> 4;
    const int rowBase = blockIdx.y * BM;
    const int colBase = blockIdx.x * BN;

    const float* Aptr = A + (size_t)rowBase * Kd;
    const float* Bptr = B + colBase;

    float acc[8][8];
    #pragma unroll
    for (int i = 0; i < 8; i++)
        #pragma unroll
        for (int j = 0; j < 8; j++) acc[i][j] = 0.f;

    // per-thread load coordinates (2 float4 each for A and B tile)
    int aRow[2], aCg[2], bKr[2], bCg[2];
    #pragma unroll
    for (int i = 0; i < 2; i++) {
        int id = tid + 256 * i;               // 0..511
        aRow[i] = id >> 2;                    // 0..127
        aCg[i]  = (id & 3) * 4;               // 0,4,8,12
        bKr[i]  = id >> 5;                    // 0..15
        bCg[i]  = (id & 31) * 4;              // 0..124
    }

    float4 aReg[2], bReg[2];
    #pragma unroll
    for (int i = 0; i < 2; i++) {
        aReg[i] = *(const float4*)(Aptr + (size_t)aRow[i] * Kd + aCg[i]);
        bReg[i] = *(const float4*)(Bptr + (size_t)bKr[i] * Nc + bCg[i]);
    }

    for (int k0 = 0; k0 < Kd; k0 += BK) {
        // stage -> shared (A transposed)
        #pragma unroll
        for (int i = 0; i < 2; i++) {
            As[aCg[i] + 0][aRow[i]] = aReg[i].x;
            As[aCg[i] + 1][aRow[i]] = aReg[i].y;
            As[aCg[i] + 2][aRow[i]] = aReg[i].z;
            As[aCg[i] + 3][aRow[i]] = aReg[i].w;
            *(float4*)&Bs[bKr[i]][bCg[i]] = bReg[i];
        }
        __syncthreads();

        // prefetch next K-tile into registers
        int k1 = k0 + BK;
        if (k1 < Kd) {
            #pragma unroll
            for (int i = 0; i < 2; i++) {
                aReg[i] = *(const float4*)(Aptr + (size_t)aRow[i] * Kd + k1 + aCg[i]);
                bReg[i] = *(const float4*)(Bptr + (size_t)(k1 + bKr[i]) * Nc + bCg[i]);
            }
        }

        // compute
        #pragma unroll
        for (int kk = 0; kk < BK; kk++) {
            float a[8], b[8];
            *(float4*)&a[0] = *(const float4*)&As[kk][ty * 8];
            *(float4*)&a[4] = *(const float4*)&As[kk][ty * 8 + 4];
            *(float4*)&b[0] = *(const float4*)&Bs[kk][tx * 8];
            *(float4*)&b[4] = *(const float4*)&Bs[kk][tx * 8 + 4];
            #pragma unroll
            for (int i = 0; i < 8; i++)
                #pragma unroll
                for (int j = 0; j < 8; j++)
                    acc[i][j] = fmaf(a[i], b[j], acc[i][j]);
        }
        __syncthreads();
    }

    // epilogue
    const size_t r0 = (size_t)rowBase + (size_t)ty * 8;
    const int    c0 = colBase + tx * 8;
    float bb[8];
    if (MODE >= 1) {
        #pragma unroll
        for (int j = 0; j < 8; j++) bb[j] = bias[c0 + j];
    }
    #pragma unroll
    for (int i = 0; i < 8; i++) {
        float* Cr = C + (r0 + i) * Nc + c0;
        #pragma unroll
        for (int j = 0; j < 8; j += 4) {
            float4 v;
            v.x = acc[i][j + 0]; v.y = acc[i][j + 1];
            v.z = acc[i][j + 2]; v.w = acc[i][j + 3];
            if (MODE >= 1) { v.x += bb[j]; v.y += bb[j+1]; v.z += bb[j+2]; v.w += bb[j+3]; }
            if (MODE == 1) {
                v.x = fmaxf(v.x, 0.f); v.y = fmaxf(v.y, 0.f);
                v.z = fmaxf(v.z, 0.f); v.w = fmaxf(v.w, 0.f);
            }
            if (MODE == 2) {
                float4 rr = *(const float4*)(res + (r0 + i) * Nc + c0 + j);
                v.x += rr.x; v.y += rr.y; v.z += rr.z; v.w += rr.w;
            }
            *(float4*)(Cr + j) = v;
        }
    }
}

// ---------------- per-node 16-head attention ---------------------------------
// One block (64 threads) per node. scores = QK^T/8, softmax rows, attn = P@V.
__global__ __launch_bounds__(64)
void attn_k(const float* __restrict__ Q, const float* __restrict__ Kmat,
            const float* __restrict__ V, float* __restrict__ O)
{
    __shared__ float q[16][68];
    __shared__ float kT[16][68];
    __shared__ float v[1024];
    __shared__ float p[16][17];

    const int n = blockIdx.x;
    const size_t base = (size_t)n * DMODEL;
    const int t = threadIdx.x;   // 0..63

    for (int idx = t; idx < 1024; idx += 64) {
        int hh = idx >> 6, d = idx & 63;
        q [hh][d] = Q   [base + idx];
        kT[hh][d] = Kmat[base + idx];
    }
    for (int i4 = t; i4 < 256; i4 += 64)
        ((float4*)v)[i4] = ((const float4*)(V + base))[i4];
    __syncthreads();

    #pragma unroll
    for (int s = t; s < 256; s += 64) {
        int i = s >> 4, j = s & 15;
        float a = 0.f;
        #pragma unroll
        for (int d = 0; d < 64; d++) a = fmaf(q[i][d], kT[j][d], a);
        p[i][j] = a * 0.125f;
    }
    __syncthreads();

    if (t < 16) {
        float m = -3.402823e38f;
        #pragma unroll
        for (int j = 0; j < 16; j++) m = fmaxf(m, p[t][j]);
        float sum = 0.f;
        #pragma unroll
        for (int j = 0; j < 16; j++) { float e = expf(p[t][j] - m); p[t][j] = e; sum += e; }
        float inv = 1.f / sum;
        #pragma unroll
        for (int j = 0; j < 16; j++) p[t][j] *= inv;
    }
    __syncthreads();

    #pragma unroll
    for (int i = 0; i < 16; i++) {
        float a = 0.f;
        #pragma unroll
        for (int j = 0; j < 16; j++) a = fmaf(p[i][j], v[j * 64 + t], a);
        O[base + (size_t)i * 64 + t] = a;
    }
}

// ---------------- batch norm (deterministic two-pass) ------------------------
__global__ void bn_partial(const float* __restrict__ x, float* __restrict__ part)
{
    const int tx = threadIdx.x, ty = threadIdx.y;   // block (32,8)
    const int col = blockIdx.x * 32 + tx;
    float s = 0.f, q = 0.f;
    for (int r = blockIdx.y * 8 + ty; r < NTOK; r += PB * 8) {
        float v = x[(size_t)r * DMODEL + col];
        s += v;
        q = fmaf(v, v, q);
    }
    __shared__ float shs[8][32], shq[8][32];
    shs[ty][tx] = s; shq[ty][tx] = q;
    __syncthreads();
    if (ty == 0) {
        #pragma unroll
        for (int yy = 1; yy < 8; yy++) { s += shs[yy][tx]; q += shq[yy][tx]; }
        part[(size_t)(blockIdx.y * 2 + 0) * DMODEL + col] = s;
        part[(size_t)(blockIdx.y * 2 + 1) * DMODEL + col] = q;
    }
}

__global__ void bn_finalize(const float* __restrict__ part,
                            const float* __restrict__ gamma, const float* __restrict__ beta,
                            float* __restrict__ sc, float* __restrict__ sh)
{
    int col = blockIdx.x * 256 + threadIdx.x;
    float s = 0.f, q = 0.f;
    for (int p = 0; p < PB; p++) {
        s += part[(size_t)(p * 2 + 0) * DMODEL + col];
        q += part[(size_t)(p * 2 + 1) * DMODEL + col];
    }
    const float inv = 1.f / (float)NTOK;
    float mu  = s * inv;
    float var = q * inv - mu * mu;
    float a = gamma[col] * rsqrtf(var + EPSBN);
    sc[col] = a;
    sh[col] = beta[col] - mu * a;
}

__global__ void bn_apply(const float* __restrict__ x, const float* __restrict__ sc,
                         const float* __restrict__ sh, float* __restrict__ y)
{
    size_t i = (size_t)blockIdx.x * 256 + threadIdx.x;   // float4 index
    int c = (int)((i * 4) & (DMODEL - 1));
    float4 xv = ((const float4*)x)[i];
    float4 a = *(const float4*)(sc + c);
    float4 b = *(const float4*)(sh + c);
    float4 r;
    r.x = fmaf(xv.x, a.x, b.x);
    r.y = fmaf(xv.y, a.y, b.y);
    r.z = fmaf(xv.z, a.z, b.z);
    r.w = fmaf(xv.w, a.w, b.w);
    ((float4*)y)[i] = r;
}

// ---------------- launch ------------------------------------------------------
extern "C" void kernel_launch(void* const* d_in, const int* in_sizes, int n_in,
                              void* d_out, int out_size)
{
    const float* h   = (const float*)d_in[0];
    const float* Wq  = (const float*)d_in[1];
    const float* Wk  = (const float*)d_in[2];
    const float* Wv  = (const float*)d_in[3];
    const float* Wo  = (const float*)d_in[4];
    const float* bo  = (const float*)d_in[5];
    const float* g1  = (const float*)d_in[6];
    const float* b1  = (const float*)d_in[7];
    const float* W1  = (const float*)d_in[8];
    const float* bf1 = (const float*)d_in[9];
    const float* W2  = (const float*)d_in[10];
    const float* bf2 = (const float*)d_in[11];
    const float* g2  = (const float*)d_in[12];
    const float* b2  = (const float*)d_in[13];
    float* out = (float*)d_out;

    float *SCR, *PARTp, *SCp, *SHp;
    cudaGetSymbolAddress((void**)&SCR,   g_scratch);
    cudaGetSymbolAddress((void**)&PARTp, g_part);
    cudaGetSymbolAddress((void**)&SCp,   g_scale);
    cudaGetSymbolAddress((void**)&SHp,   g_shift);

    // Slot multiplexing (each slot ND floats = 256MB):
    //   S0: Q          -> pre1        -> pre2
    //   S1: K          -> x (post-BN1, also FFN residual)
    //   S2: V          -> ff1 lower half
    //   S3: attn       -> ff1 upper half   (ff1 = S2..S3 contiguous, 512MB)
    float* S0 = SCR + 0 * ND;
    float* S1 = SCR + 1 * ND;
    float* S2 = SCR + 2 * ND;
    float* S3 = SCR + 3 * ND;

    const dim3 tb(256);
    const dim3 gD(DMODEL / BN, NTOK / BM);   // (8, 512)
    const dim3 gF(FFDIM  / BN, NTOK / BM);   // (16, 512)
    const dim3 bnB(32, 8);
    const dim3 bnG(DMODEL / 32, PB);
    const int  ewGrid = (int)(ND / 4 / 256); // 65536

    // Q/K/V projections
    sgemm_k<0><<<gD, tb>>>(h, Wq, nullptr, nullptr, S0, DMODEL, DMODEL);
    sgemm_k<0><<<gD, tb>>>(h, Wk, nullptr, nullptr, S1, DMODEL, DMODEL);
    sgemm_k<0><<<gD, tb>>>(h, Wv, nullptr, nullptr, S2, DMODEL, DMODEL);

    // per-node head attention: (Q=S0, K=S1, V=S2) -> attn=S3
    attn_k<<<NTOK, 64>>>(S0, S1, S2, S3);

    // output projection + bias + residual(h): attn(S3) @ Wo -> pre1 = S0
    sgemm_k<2><<<gD, tb>>>(S3, Wo, bo, h, S0, DMODEL, DMODEL);

    // BN1: pre1(S0) -> x(S1)
    bn_partial <<<bnG, bnB>>>(S0, PARTp);
    bn_finalize<<<DMODEL / 256, 256>>>(PARTp, g1, b1, SCp, SHp);
    bn_apply   <<<ewGrid, 256>>>(S0, SCp, SHp, S1);

    // FFN: x(S1) @ W1 -> ff1(S2, spans S2..S3, 512MB); relu fused
    sgemm_k<1><<<gF, tb>>>(S1, W1, bf1, nullptr, S2, DMODEL, FFDIM);
    // ff1 @ W2 + bf2 + x(S1) -> pre2 = S0
    sgemm_k<2><<<gD, tb>>>(S2, W2, bf2, S1, S0, FFDIM, DMODEL);

    // BN2: pre2(S0) -> output
    bn_partial <<<bnG, bnB>>>(S0, PARTp);
    bn_finalize<<<DMODEL / 256, 256>>>(PARTp, g2, b2, SCp, SHp);
    bn_apply   <<<ewGrid, 256>>>(S0, SCp, SHp, out);
}